// round 11
// baseline (speedup 1.0000x reference)
#include <cuda_runtime.h>
#include <cuda_bf16.h>
#include <float.h>

// Problem constants
#define BB    4
#define CC    3
#define HH    512
#define WW    512
#define TILE  16
#define RR    8
#define NTH   32          // H / TILE
#define NTW   32          // W / TILE
#define WIN   32          // TILE + 2*R
#define ND    17          // 2*R + 1
#define WPITCH 36         // padded window pitch (floats), 144B: 8B/16B aligned rows

#define NTHREADS 160      // 5 warps; 153 active compute lanes (95.6% packing)
#define NUNITS   153      // 3 i-thirds x 3 channels x 17 dy

#define NOFF_ELEMS (BB * 2 * NTH * NTW)   // 8192, new_off goes first in d_out

#define ABS2_MASK 0x7FFFFFFF7FFFFFFFULL

__device__ __forceinline__ unsigned long long addf32x2(unsigned long long a,
                                                       unsigned long long b)
{
    unsigned long long r;
    asm("add.rn.f32x2 %0, %1, %2;" : "=l"(r) : "l"(a), "l"(b));
    return r;
}

__global__ __launch_bounds__(NTHREADS, 4)
void tile_matching_kernel(const float* __restrict__ src,
                          const float* __restrict__ dst,
                          const int*   __restrict__ offset,
                          float*       __restrict__ out)
{
    const int tileId = blockIdx.x;            // b*1024 + th*32 + tw
    const int b  = tileId >> 10;
    const int th = (tileId >> 5) & 31;
    const int tw = tileId & 31;
    const int t  = threadIdx.x;

    __shared__ float sw  [CC][WIN][WPITCH];   // 32x32 window per channel (zero padded OOB)
    __shared__ float swsh[CC][WIN][WPITCH];   // shifted copy: swsh[x] = sw[x+1] (x<=30)
    __shared__ unsigned long long ssplat[CC][TILE][TILE];  // f32x2 {-s, -s}
    __shared__ float part3[3][CC][ND][ND];    // per-(i-third, channel) candidate costs
    __shared__ float bestC[ND];
    __shared__ int   bestD[ND];
    __shared__ int   s_best;

    // tile offsets (same address across block -> broadcast load)
    const int offy = offset[((b * 2 + 0) * NTH + th) * NTW + tw];
    const int offx = offset[((b * 2 + 1) * NTH + th) * NTW + tw];

    const int ti = th * TILE;
    const int tj = tw * TILE;

    // ---- Load 3x32x32 window from dst (zero for OOB == reference's zero padding) ----
    // Also populate the 1-float-shifted copy for aligned odd-start f32x2 pairs.
    for (int idx = t; idx < CC * WIN * WIN; idx += NTHREADS) {
        const int c  = idx >> 10;             // /1024
        const int wy = (idx >> 5) & 31;
        const int wx = idx & 31;
        const int gy = ti + offy - RR + wy;
        const int gx = tj + offx - RR + wx;
        float v = 0.0f;
        if (gy >= 0 && gy < HH && gx >= 0 && gx < WW)
            v = dst[((b * CC + c) * HH + gy) * WW + gx];
        sw[c][wy][wx] = v;
        if (wx >= 1) swsh[c][wy][wx - 1] = v;
    }
    // ---- Load 3x16x16 src tile as negated f32x2 splats {-s, -s} ----
    for (int idx = t; idx < CC * TILE * TILE; idx += NTHREADS) {
        const int c = idx >> 8;
        const int i = (idx >> 4) & 15;
        const int j = idx & 15;
        const float ns = -src[((b * CC + c) * HH + ti + i) * WW + tj + j];
        const unsigned int u = __float_as_uint(ns);
        ssplat[c][i][j] = ((unsigned long long)u << 32) | (unsigned long long)u;
    }
    __syncthreads();

    // ---- SAD over 17x17 candidates, packed f32x2 over dx pairs.
    // Unit u = third*51 + c*17 + dy, u < 153, i-range {0..5},{6..10},{11..15}.
    // For dx pair (2p, 2p+1) and inner j:
    //   operand pair {w[2p+j], w[2p+j+1]}: j even -> aligned LDS.64 from sw,
    //                                      j odd  -> aligned LDS.64 from swsh.
    //   diff  = add.rn.f32x2(v, {-s[j],-s[j]})   (fma pipe)
    //   |diff| via 64-bit AND                    (alu pipe, 2x LOP3)
    //   acc2 += diff                             (fma pipe)
    // Per-dx accumulation order (j ascending) identical to scalar -> bitwise
    // identical costs, so argmin/tie-break semantics are unchanged.
    if (t < NUNITS) {
        const int third = t / 51;
        const int r     = t - third * 51;
        const int c     = r / ND;
        const int dy    = r - c * ND;
        const int i0    = (third == 0) ? 0 : (third == 1 ? 6 : 11);
        const int ni    = (third == 0) ? 6 : 5;

        unsigned long long acc2[8];
#pragma unroll
        for (int p = 0; p < 8; ++p) acc2[p] = 0ULL;   // {0.0f, 0.0f}
        float acc16 = 0.0f;                           // dx = 16 scalar chain

        for (int ii = 0; ii < ni; ++ii) {
            const int i   = i0 + ii;
            const int row = dy + i;

            // Register-cache both pair alignments for this window row.
            const unsigned long long* we =
                reinterpret_cast<const unsigned long long*>(&sw[c][row][0]);
            const unsigned long long* wo =
                reinterpret_cast<const unsigned long long*>(&swsh[c][row][0]);
            unsigned long long ve[15], vo[15];
#pragma unroll
            for (int k = 0; k < 15; ++k) { ve[k] = we[k]; vo[k] = wo[k]; }
            const float* wrow = &sw[c][row][0];

#pragma unroll
            for (int j = 0; j < TILE; ++j) {
                const unsigned long long s2 = ssplat[c][i][j];
                const float ns = __uint_as_float((unsigned int)s2);  // low half = -s[j]

                // scalar dx = 16
                const float t16 = wrow[16 + j] + ns;
                acc16 += fabsf(t16);

#pragma unroll
                for (int p = 0; p < 8; ++p) {
                    const unsigned long long v =
                        (j & 1) ? vo[p + (j - 1) / 2] : ve[p + j / 2];
                    unsigned long long d = addf32x2(v, s2);
                    d &= ABS2_MASK;                    // packed |.|
                    acc2[p] = addf32x2(acc2[p], d);
                }
            }
        }

#pragma unroll
        for (int p = 0; p < 8; ++p) {
            part3[third][c][dy][2 * p + 0] =
                __uint_as_float((unsigned int)acc2[p]);          // lo = dx 2p
            part3[third][c][dy][2 * p + 1] =
                __uint_as_float((unsigned int)(acc2[p] >> 32));  // hi = dx 2p+1
        }
        part3[third][c][dy][16] = acc16;
    }
    __syncthreads();

    // ---- reduce (thirds, channels) + argmin over dx per dy.
    // Fixed order; ascending dx with strict '<' keeps the FIRST minimum,
    // matching the reference scan's (cost < best_c) update over ascending d.
    if (t < ND) {
        const int dy = t;
        float bc = FLT_MAX;
        int   bd = 0;
        for (int dx = 0; dx < ND; ++dx) {
            const float c0 = part3[0][0][dy][dx] + part3[1][0][dy][dx] + part3[2][0][dy][dx];
            const float c1 = part3[0][1][dy][dx] + part3[1][1][dy][dx] + part3[2][1][dy][dx];
            const float c2 = part3[0][2][dy][dx] + part3[1][2][dy][dx] + part3[2][2][dy][dx];
            const float cst = c0 + c1 + c2;
            const int d = dy * ND + dx;
            if (cst < bc) { bc = cst; bd = d; }
        }
        bestC[dy] = bc;
        bestD[dy] = bd;
    }
    __syncthreads();

    // ---- final argmin over dy: lexicographic (cost, d) => smallest d on exact tie ----
    if (t == 0) {
        float bc = bestC[0];
        int   bd = bestD[0];
        for (int k = 1; k < ND; ++k) {
            if (bestC[k] < bc || (bestC[k] == bc && bestD[k] < bd)) {
                bc = bestC[k];
                bd = bestD[k];
            }
        }
        s_best = bd;
        const int dy_ = bd / ND - RR;
        const int dx_ = bd % ND - RR;
        out[((b * 2 + 0) * NTH + th) * NTW + tw] = (float)(offy + dy_);
        out[((b * 2 + 1) * NTH + th) * NTW + tw] = (float)(offx + dx_);
    }
    __syncthreads();

    // ---- write aligned tile: sub-window [wy0..wy0+15][wx0..wx0+15] of sw ----
    const int bd  = s_best;
    const int wy0 = bd / ND;    // dy_ + R
    const int wx0 = bd % ND;    // dx_ + R
    for (int idx = t; idx < CC * TILE * TILE; idx += NTHREADS) {
        const int c = idx >> 8;
        const int i = (idx >> 4) & 15;
        const int j = idx & 15;
        out[NOFF_ELEMS + ((b * CC + c) * HH + ti + i) * WW + tj + j] =
            sw[c][wy0 + i][wx0 + j];
    }
}

extern "C" void kernel_launch(void* const* d_in, const int* in_sizes, int n_in,
                              void* d_out, int out_size)
{
    const float* src    = (const float*)d_in[0];
    const float* dst    = (const float*)d_in[1];
    const int*   offset = (const int*)d_in[2];
    float*       out    = (float*)d_out;

    dim3 grid(BB * NTH * NTW);   // 4096 tiles
    dim3 block(NTHREADS);
    tile_matching_kernel<<<grid, block>>>(src, dst, offset, out);
}

// round 12
// speedup vs baseline: 1.1146x; 1.1146x over previous
#include <cuda_runtime.h>
#include <cuda_bf16.h>
#include <float.h>

// Problem constants
#define BB    4
#define CC    3
#define HH    512
#define WW    512
#define TILE  16
#define RR    8
#define NTH   32          // H / TILE
#define NTW   32          // W / TILE
#define WIN   32          // TILE + 2*R
#define ND    17          // 2*R + 1
#define WPITCH 36         // padded window pitch (floats), 144B: 16B aligned

#define NTHREADS 160      // 5 warps; 153 active compute lanes (95.6% packing)
#define NUNITS   153      // 3 i-thirds x 3 channels x 17 dy

#define NOFF_ELEMS (BB * 2 * NTH * NTW)   // 8192, new_off goes first in d_out

// w - s via FFMA-imm (rt_SMSP=1, vs FADD rt=2): d = w * 1.0f + ns, ns = -s.
// IEEE-exact: multiply by 1.0 is exact, single rounding == FADD(w, -s).
__device__ __forceinline__ float sub_via_ffma_imm(float w, float ns)
{
    float d;
    asm("fma.rn.f32 %0, %1, 0f3F800000, %2;" : "=f"(d) : "f"(w), "f"(ns));
    return d;
}

__global__ __launch_bounds__(NTHREADS, 4)
void tile_matching_kernel(const float* __restrict__ src,
                          const float* __restrict__ dst,
                          const int*   __restrict__ offset,
                          float*       __restrict__ out)
{
    const int tileId = blockIdx.x;            // b*1024 + th*32 + tw
    const int b  = tileId >> 10;
    const int th = (tileId >> 5) & 31;
    const int tw = tileId & 31;
    const int t  = threadIdx.x;

    __shared__ float sw[CC][WIN][WPITCH];     // 32x32 window per channel (zero padded OOB)
    __shared__ float ss[CC][TILE][TILE];      // NEGATED src tile (-s)
    __shared__ float part3[3][CC][ND][ND];    // per-(i-third, channel) candidate costs
    __shared__ float bestC[ND];
    __shared__ int   bestD[ND];
    __shared__ int   s_best;

    // tile offsets (same address across block -> broadcast load)
    const int offy = offset[((b * 2 + 0) * NTH + th) * NTW + tw];
    const int offx = offset[((b * 2 + 1) * NTH + th) * NTW + tw];

    const int ti = th * TILE;
    const int tj = tw * TILE;

    // ---- Load 3x32x32 window from dst (zero for OOB == reference's zero padding) ----
    for (int idx = t; idx < CC * WIN * WIN; idx += NTHREADS) {
        const int c  = idx >> 10;             // /1024
        const int wy = (idx >> 5) & 31;
        const int wx = idx & 31;
        const int gy = ti + offy - RR + wy;
        const int gx = tj + offx - RR + wx;
        float v = 0.0f;
        if (gy >= 0 && gy < HH && gx >= 0 && gx < WW)
            v = dst[((b * CC + c) * HH + gy) * WW + gx];
        sw[c][wy][wx] = v;
    }
    // ---- Load 3x16x16 src tile, negated ----
    for (int idx = t; idx < CC * TILE * TILE; idx += NTHREADS) {
        const int c = idx >> 8;
        const int i = (idx >> 4) & 15;
        const int j = idx & 15;
        ss[c][i][j] = -src[((b * CC + c) * HH + ti + i) * WW + tj + j];
    }
    __syncthreads();

    // ---- SAD over 17x17 candidates.
    // Unit u = third*51 + c*17 + dy, u < 153. i-ranges {0..5},{6..10},{11..15};
    // third = u/51 keeps each warp i-range-homogeneous.
    // Per pixel: FFMA-imm (1 fma-cyc) + FADD |.| (2 fma-cyc) = 3 fma-cyc,
    // vs 4 for the FADD+FADD baseline. 17 independent chains -> issue-bound.
    if (t < NUNITS) {
        const int third = t / 51;
        const int r     = t - third * 51;
        const int c     = r / ND;
        const int dy    = r - c * ND;
        const int i0    = (third == 0) ? 0 : (third == 1 ? 6 : 11);
        const int ni    = (third == 0) ? 6 : 5;

        float acc[ND];
#pragma unroll
        for (int dx = 0; dx < ND; ++dx) acc[dx] = 0.0f;

        for (int ii = 0; ii < ni; ++ii) {
            const int i = i0 + ii;
            // window row (dy+i): 32 floats via 8x LDS.128 (row base 16B aligned)
            float w[WIN];
            {
                const float4* wr = reinterpret_cast<const float4*>(&sw[c][dy + i][0]);
#pragma unroll
                for (int k = 0; k < 8; ++k) {
                    float4 v = wr[k];
                    w[4 * k + 0] = v.x; w[4 * k + 1] = v.y;
                    w[4 * k + 2] = v.z; w[4 * k + 3] = v.w;
                }
            }
            // negated src row i: 16 floats (broadcast among lanes sharing (c,i))
            float s[TILE];
            {
                const float4* sr = reinterpret_cast<const float4*>(&ss[c][i][0]);
#pragma unroll
                for (int k = 0; k < 4; ++k) {
                    float4 v = sr[k];
                    s[4 * k + 0] = v.x; s[4 * k + 1] = v.y;
                    s[4 * k + 2] = v.z; s[4 * k + 3] = v.w;
                }
            }
#pragma unroll
            for (int dx = 0; dx < ND; ++dx) {
#pragma unroll
                for (int j = 0; j < TILE; ++j) {
                    const float d = sub_via_ffma_imm(w[dx + j], s[j]);
                    acc[dx] += fabsf(d);    // FADD with |.| source modifier
                }
            }
        }
#pragma unroll
        for (int dx = 0; dx < ND; ++dx) part3[third][c][dy][dx] = acc[dx];
    }
    __syncthreads();

    // ---- reduce (thirds, channels) + argmin over dx per dy.
    // Fixed order; ascending dx with strict '<' keeps the FIRST minimum,
    // matching the reference scan's (cost < best_c) update over ascending d.
    if (t < ND) {
        const int dy = t;
        float bc = FLT_MAX;
        int   bd = 0;
        for (int dx = 0; dx < ND; ++dx) {
            const float c0 = part3[0][0][dy][dx] + part3[1][0][dy][dx] + part3[2][0][dy][dx];
            const float c1 = part3[0][1][dy][dx] + part3[1][1][dy][dx] + part3[2][1][dy][dx];
            const float c2 = part3[0][2][dy][dx] + part3[1][2][dy][dx] + part3[2][2][dy][dx];
            const float cst = c0 + c1 + c2;
            const int d = dy * ND + dx;
            if (cst < bc) { bc = cst; bd = d; }
        }
        bestC[dy] = bc;
        bestD[dy] = bd;
    }
    __syncthreads();

    // ---- final argmin over dy: lexicographic (cost, d) => smallest d on exact tie ----
    if (t == 0) {
        float bc = bestC[0];
        int   bd = bestD[0];
        for (int k = 1; k < ND; ++k) {
            if (bestC[k] < bc || (bestC[k] == bc && bestD[k] < bd)) {
                bc = bestC[k];
                bd = bestD[k];
            }
        }
        s_best = bd;
        const int dy_ = bd / ND - RR;
        const int dx_ = bd % ND - RR;
        out[((b * 2 + 0) * NTH + th) * NTW + tw] = (float)(offy + dy_);
        out[((b * 2 + 1) * NTH + th) * NTW + tw] = (float)(offx + dx_);
    }
    __syncthreads();

    // ---- write aligned tile: sub-window [wy0..wy0+15][wx0..wx0+15] of sw ----
    const int bd  = s_best;
    const int wy0 = bd / ND;    // dy_ + R
    const int wx0 = bd % ND;    // dx_ + R
    for (int idx = t; idx < CC * TILE * TILE; idx += NTHREADS) {
        const int c = idx >> 8;
        const int i = (idx >> 4) & 15;
        const int j = idx & 15;
        out[NOFF_ELEMS + ((b * CC + c) * HH + ti + i) * WW + tj + j] =
            sw[c][wy0 + i][wx0 + j];
    }
}

extern "C" void kernel_launch(void* const* d_in, const int* in_sizes, int n_in,
                              void* d_out, int out_size)
{
    const float* src    = (const float*)d_in[0];
    const float* dst    = (const float*)d_in[1];
    const int*   offset = (const int*)d_in[2];
    float*       out    = (float*)d_out;

    dim3 grid(BB * NTH * NTW);   // 4096 tiles
    dim3 block(NTHREADS);
    tile_matching_kernel<<<grid, block>>>(src, dst, offset, out);
}